// round 4
// baseline (speedup 1.0000x reference)
#include <cuda_runtime.h>
#include <cstdio>

namespace {
constexpr int P_     = 256;
constexpr int H_     = 32;
constexpr int DM     = 2048;
constexpr int HD     = 64;
constexpr int PATCH_ = 256;
}

// scratch (allocation-free per harness rules)
__device__ float g_vr[P_ * DM];
__device__ float g_vi[P_ * DM];
__device__ float g_yr[P_ * DM];
__device__ float g_yi[P_ * DM];

__device__ __forceinline__ int clampi(int i, int sz) { return i < sz ? i : sz - 1; }

// ---------------------------------------------------------------------------
// Kernel 1: vr = x @ vR_k + vR_b ; vi = x @ vI_k + vI_b
// M=256, K=256, N=2048. grid = (N/64, M/64, 2), 256 threads, 4x4 per thread.
// ---------------------------------------------------------------------------
__global__ void gemm_v(const float* __restrict__ x, int sx,
                       const float* __restrict__ Wr,
                       const float* __restrict__ br,
                       const float* __restrict__ Wi,
                       const float* __restrict__ bi, int sw, int sb)
{
    constexpr int K = PATCH_, N = DM;
    const float* W = blockIdx.z ? Wi : Wr;
    const float* b = blockIdx.z ? bi : br;
    float* C       = blockIdx.z ? g_vi : g_vr;

    __shared__ __align__(16) float As[64][17];
    __shared__ __align__(16) float Bs[16][64];

    const int tid = threadIdx.x;
    const int tx = tid & 15, ty = tid >> 4;
    const int row0 = blockIdx.y * 64, col0 = blockIdx.x * 64;

    float acc[4][4] = {};

    for (int k0 = 0; k0 < K; k0 += 16) {
        #pragma unroll
        for (int l = 0; l < 4; l++) {
            int idx = tid + l * 256;
            As[idx >> 4][idx & 15] =
                x[clampi((row0 + (idx >> 4)) * K + k0 + (idx & 15), sx)];
        }
        #pragma unroll
        for (int l = 0; l < 4; l++) {
            int idx = tid + l * 256;
            Bs[idx >> 6][idx & 63] =
                W[clampi((k0 + (idx >> 6)) * N + col0 + (idx & 63), sw)];
        }
        __syncthreads();

        #pragma unroll
        for (int kk = 0; kk < 16; kk++) {
            float a[4];
            #pragma unroll
            for (int i = 0; i < 4; i++) a[i] = As[ty * 4 + i][kk];
            float4 bv = *(const float4*)&Bs[kk][tx * 4];
            float bb[4] = {bv.x, bv.y, bv.z, bv.w};
            #pragma unroll
            for (int i = 0; i < 4; i++)
                #pragma unroll
                for (int j = 0; j < 4; j++)
                    acc[i][j] = fmaf(a[i], bb[j], acc[i][j]);
        }
        __syncthreads();
    }

    #pragma unroll
    for (int i = 0; i < 4; i++) {
        int r = row0 + ty * 4 + i;
        #pragma unroll
        for (int j = 0; j < 4; j++) {
            int c = col0 + tx * 4 + j;
            C[r * N + c] = acc[i][j] + b[clampi(c, sb)];
        }
    }
}

// ---------------------------------------------------------------------------
// Kernel 2: circulant shift-attention per head.
//   att[s,h,d] = sum_q J[(q+s)%P, h] * v[q, h, d]   (complex)
// grid = (4 s-tiles, 32 heads), 256 threads. Block computes 64 s x 64 d.
// ---------------------------------------------------------------------------
__global__ void circ_att(const float* __restrict__ JR,
                         const float* __restrict__ JI, int sj)
{
    const int h  = blockIdx.y;
    const int s0 = blockIdx.x * 64;

    __shared__ __align__(16) float jr_s[512];
    __shared__ __align__(16) float ji_s[512];
    __shared__ __align__(16) float vr_s[64][64];
    __shared__ __align__(16) float vi_s[64][64];

    const int tid = threadIdx.x;
    const int tx = tid & 15, ty = tid >> 4;

    // J duplicated to length 512 so (q + s) indexes without modulo
    for (int t = tid; t < 512; t += 256) {
        int ji = clampi((t & 255) * H_ + h, sj);
        jr_s[t] = JR[ji];
        ji_s[t] = JI[ji];
    }

    float accR[4][4] = {}, accI[4][4] = {};

    for (int q0 = 0; q0 < P_; q0 += 64) {
        __syncthreads();   // J visible (first iter) / prev compute done
        #pragma unroll
        for (int l = 0; l < 16; l++) {
            int idx = tid + l * 256;                 // 4096 elems
            int qq = idx >> 6, d = idx & 63;
            int gi = (q0 + qq) * DM + h * HD + d;    // provably < P_*DM
            vr_s[qq][d] = g_vr[gi];
            vi_s[qq][d] = g_vi[gi];
        }
        __syncthreads();

        #pragma unroll 4
        for (int kk = 0; kk < 64; kk++) {
            int q = q0 + kk;
            float jr[4], ji[4];
            #pragma unroll
            for (int i = 0; i < 4; i++) {
                jr[i] = jr_s[q + s0 + ty * 4 + i];
                ji[i] = ji_s[q + s0 + ty * 4 + i];
            }
            float4 vr4 = *(const float4*)&vr_s[kk][tx * 4];
            float4 vi4 = *(const float4*)&vi_s[kk][tx * 4];
            float vr[4] = {vr4.x, vr4.y, vr4.z, vr4.w};
            float vi[4] = {vi4.x, vi4.y, vi4.z, vi4.w};
            #pragma unroll
            for (int i = 0; i < 4; i++)
                #pragma unroll
                for (int j = 0; j < 4; j++) {
                    accR[i][j] = fmaf(jr[i], vr[j], accR[i][j]);
                    accR[i][j] = fmaf(-ji[i], vi[j], accR[i][j]);
                    accI[i][j] = fmaf(jr[i], vi[j], accI[i][j]);
                    accI[i][j] = fmaf(ji[i], vr[j], accI[i][j]);
                }
        }
    }

    #pragma unroll
    for (int i = 0; i < 4; i++) {
        int s = s0 + ty * 4 + i;
        #pragma unroll
        for (int j = 0; j < 4; j++) {
            int d = tx * 4 + j;
            g_yr[s * DM + h * HD + d] = accR[i][j];
            g_yi[s * DM + h * HD + d] = accI[i][j];
        }
    }
}

// ---------------------------------------------------------------------------
// Kernel 3: fused complex output projection + log_cosh.
//   mode 0: write Re(log_cosh) only, one float per element (out_size floats).
//   mode 1: write interleaved (re, im) pairs (out_size == 2*P*DM floats).
// Every write is element-guarded by out_floats — cannot overrun d_out.
// ---------------------------------------------------------------------------
__global__ void gemm_out(const float* __restrict__ WR,
                         const float* __restrict__ bR,
                         const float* __restrict__ WI,
                         const float* __restrict__ bI, int sw, int sb,
                         float* __restrict__ out, int out_floats, int mode)
{
    constexpr int K = DM, N = DM;

    __shared__ __align__(16) float yrs[64][17];
    __shared__ __align__(16) float yis[64][17];
    __shared__ __align__(16) float wrs[16][64];
    __shared__ __align__(16) float wis[16][64];

    const int tid = threadIdx.x;
    const int tx = tid & 15, ty = tid >> 4;
    const int row0 = blockIdx.y * 64, col0 = blockIdx.x * 64;

    float accR[4][4] = {}, accI[4][4] = {};

    for (int k0 = 0; k0 < K; k0 += 16) {
        #pragma unroll
        for (int l = 0; l < 4; l++) {
            int idx = tid + l * 256;
            int m = idx >> 4, kk = idx & 15;
            int gi = (row0 + m) * K + k0 + kk;       // provably < P_*DM
            yrs[m][kk] = g_yr[gi];
            yis[m][kk] = g_yi[gi];
        }
        #pragma unroll
        for (int l = 0; l < 4; l++) {
            int idx = tid + l * 256;
            int kk = idx >> 6, n = idx & 63;
            int wi = clampi((k0 + kk) * N + col0 + n, sw);
            wrs[kk][n] = WR[wi];
            wis[kk][n] = WI[wi];
        }
        __syncthreads();

        #pragma unroll
        for (int kk = 0; kk < 16; kk++) {
            float ar[4], ai[4];
            #pragma unroll
            for (int i = 0; i < 4; i++) {
                ar[i] = yrs[ty * 4 + i][kk];
                ai[i] = yis[ty * 4 + i][kk];
            }
            float4 w4r = *(const float4*)&wrs[kk][tx * 4];
            float4 w4i = *(const float4*)&wis[kk][tx * 4];
            float wr_[4] = {w4r.x, w4r.y, w4r.z, w4r.w};
            float wi_[4] = {w4i.x, w4i.y, w4i.z, w4i.w};
            #pragma unroll
            for (int i = 0; i < 4; i++)
                #pragma unroll
                for (int j = 0; j < 4; j++) {
                    accR[i][j] = fmaf(ar[i], wr_[j], accR[i][j]);
                    accR[i][j] = fmaf(-ai[i], wi_[j], accR[i][j]);
                    accI[i][j] = fmaf(ar[i], wi_[j], accI[i][j]);
                    accI[i][j] = fmaf(ai[i], wr_[j], accI[i][j]);
                }
        }
        __syncthreads();
    }

    const float LN2 = 0.69314718055994531f;
    #pragma unroll
    for (int i = 0; i < 4; i++) {
        int s = row0 + ty * 4 + i;
        #pragma unroll
        for (int j = 0; j < 4; j++) {
            int n = col0 + tx * 4 + j;
            float re = accR[i][j] + bR[clampi(n, sb)];
            float im = accI[i][j] + bI[clampi(n, sb)];
            // log_cosh(z): z' = z*sgn(re); z' + log1p(exp(-2 z')) - ln2
            float sgn = (__float_as_int(re) < 0) ? -1.0f : 1.0f;
            float a = re * sgn;
            float b = im * sgn;
            float e = expf(-2.0f * a);
            float s2, c2;
            __sincosf(2.0f * b, &s2, &c2);
            float wr = e * c2;           // Re(exp(-2 z'))
            float wi = -e * s2;          // Im(exp(-2 z'))
            float u = 1.0f + wr;
            float res_re = a + 0.5f * logf(u * u + wi * wi) - LN2;
            if (mode == 0) {
                int fi = s * N + n;
                if (fi < out_floats) out[fi] = res_re;
            } else {
                float res_im = b + atan2f(wi, u);
                int fi = (s * N + n) * 2;
                if (fi < out_floats)     out[fi]     = res_re;
                if (fi + 1 < out_floats) out[fi + 1] = res_im;
            }
        }
    }
}

extern "C" void kernel_launch(void* const* d_in, const int* in_sizes, int n_in,
                              void* d_out, int out_size)
{
    // ---- diagnostics: ground-truth sizes into the log (deterministic) ----
    fprintf(stderr, "kl-diag: n_in=%d out_size=%d sizes=", n_in, out_size);
    for (int i = 0; i < n_in; i++) fprintf(stderr, "%d,", in_sizes[i]);
    fprintf(stderr, "\n");

    // ---- classify inputs by element count (order-robust) ----
    const float* x = nullptr;   int sx = 0;
    const float* vk[2] = {};    int svk = 0;
    const float* J[2]  = {};    int sj = 0;
    const float* wk[2] = {};    int swk = 0;
    const float* bs[4] = {};    int sb = 0;
    int nvk = 0, nj = 0, nwk = 0, nb = 0;

    for (int i = 0; i < n_in; i++) {
        const float* p = (const float*)d_in[i];
        int sz = in_sizes[i];
        if      (sz == 65536   && !x)      { x = p; sx = sz; }
        else if (sz == 524288  && nvk < 2) { vk[nvk++] = p; svk = sz; }
        else if (sz == 8192    && nj  < 2) { J[nj++]   = p; sj  = sz; }
        else if (sz == 4194304 && nwk < 2) { wk[nwk++] = p; swk = sz; }
        else if (sz == 2048    && nb  < 4) { bs[nb++]  = p; sb  = sz; }
    }

    if (!(x && nvk == 2 && nj == 2 && nwk == 2 && nb == 4)) {
        if (n_in < 11) return;  // cannot resolve; do nothing (no crash)
        x     = (const float*)d_in[0];  sx  = in_sizes[0];
        vk[0] = (const float*)d_in[1];  bs[0] = (const float*)d_in[2];
        vk[1] = (const float*)d_in[3];  bs[1] = (const float*)d_in[4];
        J[0]  = (const float*)d_in[5];  J[1]  = (const float*)d_in[6];
        wk[0] = (const float*)d_in[7];  bs[2] = (const float*)d_in[8];
        wk[1] = (const float*)d_in[9];  bs[3] = (const float*)d_in[10];
        svk = in_sizes[1]; sj = in_sizes[5]; swk = in_sizes[7]; sb = in_sizes[2];
    }

    // Output interpretation. No complex dtype exists in the harness, so
    // out_size == P*DM  -> float32 real-part output (Re(log_cosh)), 2MB
    // out_size == 2*P*DM -> float32 view of interleaved complex, 4MB
    // anything else      -> real-part, guarded by out_size (never overruns)
    int mode       = (out_size == 2 * P_ * DM) ? 1 : 0;
    int out_floats = out_size;

    gemm_v  <<<dim3(DM / 64, P_ / 64, 2), 256>>>(x, sx, vk[0], bs[0], vk[1], bs[1],
                                                 svk, sb);
    circ_att<<<dim3(P_ / 64, H_),        256>>>(J[0], J[1], sj);
    gemm_out<<<dim3(DM / 64, P_ / 64),   256>>>(wk[0], bs[2], wk[1], bs[3], swk, sb,
                                                (float*)d_out, out_floats, mode);
}

// round 6
// speedup vs baseline: 1.2265x; 1.2265x over previous
#include <cuda_runtime.h>
#include <cuda_bf16.h>
#include <cstdint>

namespace {
constexpr int P_     = 256;
constexpr int H_     = 32;
constexpr int DM     = 2048;
constexpr int HD     = 64;
constexpr int PATCH_ = 256;

constexpr int BM = 64;
constexpr int BN = 64;
constexpr int KC = 32;                 // k per smem stage
constexpr int N_TILES = 3 * (DM / KC); // 3 split passes x 64 = 192
constexpr int PADK = KC + 8;           // 40 bf16 = 80B stride (16B aligned, conflict-free)
}

// ------------------------- device scratch (static) -------------------------
__device__ float g_vr[P_ * DM];
__device__ float g_vi[P_ * DM];
__device__ float g_yr[P_ * DM];
__device__ float g_yi[P_ * DM];

__device__ __nv_bfloat16 g_Yr_hi[P_ * DM];
__device__ __nv_bfloat16 g_Yr_lo[P_ * DM];
__device__ __nv_bfloat16 g_Yi_hi[P_ * DM];
__device__ __nv_bfloat16 g_Yi_lo[P_ * DM];

__device__ __nv_bfloat16 g_WtR_hi[DM * DM];   // [n][k] = w0R_k[k][n]
__device__ __nv_bfloat16 g_WtR_lo[DM * DM];
__device__ __nv_bfloat16 g_WtI_hi[DM * DM];
__device__ __nv_bfloat16 g_WtI_lo[DM * DM];

__device__ __forceinline__ int clampi(int i, int sz) { return i < sz ? i : sz - 1; }

// mma.sync m16n8k16 row.col f32 += bf16*bf16
#define MMA_BF16(d, a, b0_, b1_)                                               \
    asm volatile(                                                              \
        "mma.sync.aligned.m16n8k16.row.col.f32.bf16.bf16.f32 "                 \
        "{%0,%1,%2,%3}, {%4,%5,%6,%7}, {%8,%9}, {%0,%1,%2,%3};"                \
        : "+f"(d[0]), "+f"(d[1]), "+f"(d[2]), "+f"(d[3])                       \
        : "r"(a[0]), "r"(a[1]), "r"(a[2]), "r"(a[3]), "r"(b0_), "r"(b1_))

// ---------------------------------------------------------------------------
// Kernel 1: vr = x @ vR_k + vR_b ; vi = x @ vI_k + vI_b   (fp32)
// ---------------------------------------------------------------------------
__global__ void gemm_v(const float* __restrict__ x, int sx,
                       const float* __restrict__ Wr, const float* __restrict__ br,
                       const float* __restrict__ Wi, const float* __restrict__ bi,
                       int sw, int sb)
{
    constexpr int K = PATCH_, N = DM;
    const float* W = blockIdx.z ? Wi : Wr;
    const float* b = blockIdx.z ? bi : br;
    float* C       = blockIdx.z ? g_vi : g_vr;

    __shared__ __align__(16) float As[64][17];
    __shared__ __align__(16) float Bs[16][64];

    const int tid = threadIdx.x;
    const int tx = tid & 15, ty = tid >> 4;
    const int row0 = blockIdx.y * 64, col0 = blockIdx.x * 64;

    float acc[4][4] = {};

    for (int k0 = 0; k0 < K; k0 += 16) {
        #pragma unroll
        for (int l = 0; l < 4; l++) {
            int idx = tid + l * 256;
            As[idx >> 4][idx & 15] =
                x[clampi((row0 + (idx >> 4)) * K + k0 + (idx & 15), sx)];
        }
        #pragma unroll
        for (int l = 0; l < 4; l++) {
            int idx = tid + l * 256;
            Bs[idx >> 6][idx & 63] =
                W[clampi((k0 + (idx >> 6)) * N + col0 + (idx & 63), sw)];
        }
        __syncthreads();
        #pragma unroll
        for (int kk = 0; kk < 16; kk++) {
            float a[4];
            #pragma unroll
            for (int i = 0; i < 4; i++) a[i] = As[ty * 4 + i][kk];
            float4 bv = *(const float4*)&Bs[kk][tx * 4];
            float bb[4] = {bv.x, bv.y, bv.z, bv.w};
            #pragma unroll
            for (int i = 0; i < 4; i++)
                #pragma unroll
                for (int j = 0; j < 4; j++)
                    acc[i][j] = fmaf(a[i], bb[j], acc[i][j]);
        }
        __syncthreads();
    }

    #pragma unroll
    for (int i = 0; i < 4; i++) {
        int r = row0 + ty * 4 + i;
        #pragma unroll
        for (int j = 0; j < 4; j++) {
            int c = col0 + tx * 4 + j;
            C[r * N + c] = acc[i][j] + b[clampi(c, sb)];
        }
    }
}

// ---------------------------------------------------------------------------
// Kernel 2: circulant shift-attention (fp32)
// ---------------------------------------------------------------------------
__global__ void circ_att(const float* __restrict__ JR,
                         const float* __restrict__ JI, int sj)
{
    const int h  = blockIdx.y;
    const int s0 = blockIdx.x * 64;

    __shared__ __align__(16) float jr_s[512];
    __shared__ __align__(16) float ji_s[512];
    __shared__ __align__(16) float vr_s[64][64];
    __shared__ __align__(16) float vi_s[64][64];

    const int tid = threadIdx.x;
    const int tx = tid & 15, ty = tid >> 4;

    for (int t = tid; t < 512; t += 256) {
        int ji = clampi((t & 255) * H_ + h, sj);
        jr_s[t] = JR[ji];
        ji_s[t] = JI[ji];
    }

    float accR[4][4] = {}, accI[4][4] = {};

    for (int q0 = 0; q0 < P_; q0 += 64) {
        __syncthreads();
        #pragma unroll
        for (int l = 0; l < 16; l++) {
            int idx = tid + l * 256;
            int qq = idx >> 6, d = idx & 63;
            int gi = (q0 + qq) * DM + h * HD + d;
            vr_s[qq][d] = g_vr[gi];
            vi_s[qq][d] = g_vi[gi];
        }
        __syncthreads();

        #pragma unroll 4
        for (int kk = 0; kk < 64; kk++) {
            int q = q0 + kk;
            float jr[4], ji[4];
            #pragma unroll
            for (int i = 0; i < 4; i++) {
                jr[i] = jr_s[q + s0 + ty * 4 + i];
                ji[i] = ji_s[q + s0 + ty * 4 + i];
            }
            float4 vr4 = *(const float4*)&vr_s[kk][tx * 4];
            float4 vi4 = *(const float4*)&vi_s[kk][tx * 4];
            float vr[4] = {vr4.x, vr4.y, vr4.z, vr4.w};
            float vi[4] = {vi4.x, vi4.y, vi4.z, vi4.w};
            #pragma unroll
            for (int i = 0; i < 4; i++)
                #pragma unroll
                for (int j = 0; j < 4; j++) {
                    accR[i][j] = fmaf(jr[i], vr[j], accR[i][j]);
                    accR[i][j] = fmaf(-ji[i], vi[j], accR[i][j]);
                    accI[i][j] = fmaf(jr[i], vi[j], accI[i][j]);
                    accI[i][j] = fmaf(ji[i], vr[j], accI[i][j]);
                }
        }
    }

    #pragma unroll
    for (int i = 0; i < 4; i++) {
        int s = s0 + ty * 4 + i;
        #pragma unroll
        for (int j = 0; j < 4; j++) {
            int d = tx * 4 + j;
            g_yr[s * DM + h * HD + d] = accR[i][j];
            g_yi[s * DM + h * HD + d] = accI[i][j];
        }
    }
}

// ---------------------------------------------------------------------------
// Kernel 3a: split y panels into bf16 hi/lo
// ---------------------------------------------------------------------------
__global__ void split_y()
{
    int i = blockIdx.x * 256 + threadIdx.x;
    if (i >= P_ * DM) return;
    float a = g_yr[i];
    __nv_bfloat16 h = __float2bfloat16(a);
    g_Yr_hi[i] = h;
    g_Yr_lo[i] = __float2bfloat16(a - __bfloat162float(h));
    float b = g_yi[i];
    __nv_bfloat16 h2 = __float2bfloat16(b);
    g_Yi_hi[i] = h2;
    g_Yi_lo[i] = __float2bfloat16(b - __bfloat162float(h2));
}

// ---------------------------------------------------------------------------
// Kernel 3b: transpose + split weights: Wt[n][k] = W[k][n] -> bf16 hi/lo
// grid (64, 64), block (32, 8)
// ---------------------------------------------------------------------------
__global__ void split_wt(const float* __restrict__ W, int sw,
                         __nv_bfloat16* __restrict__ hi,
                         __nv_bfloat16* __restrict__ lo)
{
    __shared__ float t[32][33];
    const int tx = threadIdx.x, ty = threadIdx.y;
    const int n0 = blockIdx.x * 32, k0 = blockIdx.y * 32;

    #pragma unroll
    for (int i = 0; i < 4; i++) {
        int k = k0 + ty + i * 8;
        t[ty + i * 8][tx] = W[clampi(k * DM + n0 + tx, sw)];
    }
    __syncthreads();
    #pragma unroll
    for (int i = 0; i < 4; i++) {
        int n = n0 + ty + i * 8;
        float a = t[tx][ty + i * 8];
        __nv_bfloat16 h = __float2bfloat16(a);
        int oi = n * DM + k0 + tx;
        hi[oi] = h;
        lo[oi] = __float2bfloat16(a - __bfloat162float(h));
    }
}

// ---------------------------------------------------------------------------
// Kernel 4: mma.sync bf16 split GEMM + fused bias/log_cosh epilogue.
// grid (DM/BN=32, P_/BM=4), 128 threads (4 warps, 2x2 grid of 32x32 tiles).
// accRe = yr*WR + yi*(-WI);  accIm = yr*WI + yi*WR   (B-frag sign flip for -WI)
// K_eff = 3 passes x 2048 (Ootomo 3-term split).
// ---------------------------------------------------------------------------
__global__ void __launch_bounds__(128)
gemm_out_mma(const float* __restrict__ bR, const float* __restrict__ bI, int sb,
             float* __restrict__ out, int out_floats, int mode)
{
    __shared__ __nv_bfloat16 sYr[2][BM][PADK];
    __shared__ __nv_bfloat16 sYi[2][BM][PADK];
    __shared__ __nv_bfloat16 sWr[2][BN][PADK];
    __shared__ __nv_bfloat16 sWi[2][BN][PADK];

    const int tid  = threadIdx.x;
    const int wid  = tid >> 5, lane = tid & 31;
    const int g    = lane >> 2, tig = lane & 3;
    const int wm   = wid >> 1, wn = wid & 1;
    const int m0   = blockIdx.y * BM, n0 = blockIdx.x * BN;

    const int row = tid >> 1;          // 0..63
    const int v0  = (tid & 1) * 2;     // uint4 slot 0 or 2 (each row = 4 uint4)

    float accRe[2][4][4] = {};
    float accIm[2][4][4] = {};

    uint4 pre[8];

    auto load_tile = [&](int t) {
        int pass = t >> 6, kt = t & 63, k0 = kt * KC;
        const __nv_bfloat16* Ar = (pass < 2) ? g_Yr_hi : g_Yr_lo;
        const __nv_bfloat16* Ai = (pass < 2) ? g_Yi_hi : g_Yi_lo;
        const __nv_bfloat16* Br = (pass == 1) ? g_WtR_lo : g_WtR_hi;
        const __nv_bfloat16* Bi = (pass == 1) ? g_WtI_lo : g_WtI_hi;
        const __nv_bfloat16* ar = Ar + (m0 + row) * DM + k0 + v0 * 8;
        const __nv_bfloat16* ai = Ai + (m0 + row) * DM + k0 + v0 * 8;
        const __nv_bfloat16* br = Br + (n0 + row) * DM + k0 + v0 * 8;
        const __nv_bfloat16* bi = Bi + (n0 + row) * DM + k0 + v0 * 8;
        pre[0] = *(const uint4*)(ar);      pre[1] = *(const uint4*)(ar + 8);
        pre[2] = *(const uint4*)(ai);      pre[3] = *(const uint4*)(ai + 8);
        pre[4] = *(const uint4*)(br);      pre[5] = *(const uint4*)(br + 8);
        pre[6] = *(const uint4*)(bi);      pre[7] = *(const uint4*)(bi + 8);
    };
    auto store_tile = [&](int s) {
        *(uint4*)&sYr[s][row][v0 * 8]       = pre[0];
        *(uint4*)&sYr[s][row][v0 * 8 + 8]   = pre[1];
        *(uint4*)&sYi[s][row][v0 * 8]       = pre[2];
        *(uint4*)&sYi[s][row][v0 * 8 + 8]   = pre[3];
        *(uint4*)&sWr[s][row][v0 * 8]       = pre[4];
        *(uint4*)&sWr[s][row][v0 * 8 + 8]   = pre[5];
        *(uint4*)&sWi[s][row][v0 * 8]       = pre[6];
        *(uint4*)&sWi[s][row][v0 * 8 + 8]   = pre[7];
    };

    load_tile(0);
    store_tile(0);
    __syncthreads();

    for (int t = 0; t < N_TILES; t++) {
        const int s = t & 1;
        if (t + 1 < N_TILES) load_tile(t + 1);

        #pragma unroll
        for (int kk = 0; kk < KC; kk += 16) {
            uint32_t ayr[2][4], ayi[2][4];
            #pragma unroll
            for (int mm = 0; mm < 2; mm++) {
                int r0 = wm * 32 + mm * 16 + g;
                ayr[mm][0] = *(const uint32_t*)&sYr[s][r0    ][kk + tig * 2];
                ayr[mm][1] = *(const uint32_t*)&sYr[s][r0 + 8][kk + tig * 2];
                ayr[mm][2] = *(const uint32_t*)&sYr[s][r0    ][kk + tig * 2 + 8];
                ayr[mm][3] = *(const uint32_t*)&sYr[s][r0 + 8][kk + tig * 2 + 8];
                ayi[mm][0] = *(const uint32_t*)&sYi[s][r0    ][kk + tig * 2];
                ayi[mm][1] = *(const uint32_t*)&sYi[s][r0 + 8][kk + tig * 2];
                ayi[mm][2] = *(const uint32_t*)&sYi[s][r0    ][kk + tig * 2 + 8];
                ayi[mm][3] = *(const uint32_t*)&sYi[s][r0 + 8][kk + tig * 2 + 8];
            }
            #pragma unroll
            for (int nn = 0; nn < 4; nn++) {
                int bn = wn * 32 + nn * 8 + g;
                uint32_t bwr0 = *(const uint32_t*)&sWr[s][bn][kk + tig * 2];
                uint32_t bwr1 = *(const uint32_t*)&sWr[s][bn][kk + tig * 2 + 8];
                uint32_t bwi0 = *(const uint32_t*)&sWi[s][bn][kk + tig * 2];
                uint32_t bwi1 = *(const uint32_t*)&sWi[s][bn][kk + tig * 2 + 8];
                uint32_t bwn0 = bwi0 ^ 0x80008000u;
                uint32_t bwn1 = bwi1 ^ 0x80008000u;
                #pragma unroll
                for (int mm = 0; mm < 2; mm++) {
                    MMA_BF16(accRe[mm][nn], ayr[mm], bwr0, bwr1);
                    MMA_BF16(accRe[mm][nn], ayi[mm], bwn0, bwn1);
                    MMA_BF16(accIm[mm][nn], ayr[mm], bwi0, bwi1);
                    MMA_BF16(accIm[mm][nn], ayi[mm], bwr0, bwr1);
                }
            }
        }

        if (t + 1 < N_TILES) store_tile((t + 1) & 1);
        __syncthreads();
    }

    // ------------------ epilogue: bias + log_cosh (real part) ---------------
    const float LN2 = 0.69314718055994531f;
    #pragma unroll
    for (int mm = 0; mm < 2; mm++) {
        #pragma unroll
        for (int nn = 0; nn < 4; nn++) {
            int mi = m0 + wm * 32 + mm * 16 + g;
            int ni = n0 + wn * 32 + nn * 8 + tig * 2;
            #pragma unroll
            for (int c = 0; c < 4; c++) {
                int m = mi + (c >> 1) * 8;
                int n = ni + (c & 1);
                float re = accRe[mm][nn][c] + bR[clampi(n, sb)];
                float im = accIm[mm][nn][c] + bI[clampi(n, sb)];
                float sgn = (__float_as_int(re) < 0) ? -1.0f : 1.0f;
                float a = re * sgn;
                float b = im * sgn;
                float e = expf(-2.0f * a);
                float s2, c2;
                __sincosf(2.0f * b, &s2, &c2);
                float wr = e * c2, wi = -e * s2;
                float u = 1.0f + wr;
                float res_re = a + 0.5f * logf(u * u + wi * wi) - LN2;
                if (mode == 0) {
                    int fi = m * DM + n;
                    if (fi < out_floats) out[fi] = res_re;
                } else {
                    float res_im = b + atan2f(wi, u);
                    int fi = (m * DM + n) * 2;
                    if (fi < out_floats)     out[fi]     = res_re;
                    if (fi + 1 < out_floats) out[fi + 1] = res_im;
                }
            }
        }
    }
}

// ---------------------------------------------------------------------------
extern "C" void kernel_launch(void* const* d_in, const int* in_sizes, int n_in,
                              void* d_out, int out_size)
{
    const float* x = nullptr;   int sx = 0;
    const float* vk[2] = {};    int svk = 0;
    const float* J[2]  = {};    int sj = 0;
    const float* wk[2] = {};    int swk = 0;
    const float* bs[4] = {};    int sb = 0;
    int nvk = 0, nj = 0, nwk = 0, nb = 0;

    for (int i = 0; i < n_in; i++) {
        const float* p = (const float*)d_in[i];
        int sz = in_sizes[i];
        if      (sz == 65536   && !x)      { x = p; sx = sz; }
        else if (sz == 524288  && nvk < 2) { vk[nvk++] = p; svk = sz; }
        else if (sz == 8192    && nj  < 2) { J[nj++]   = p; sj  = sz; }
        else if (sz == 4194304 && nwk < 2) { wk[nwk++] = p; swk = sz; }
        else if (sz == 2048    && nb  < 4) { bs[nb++]  = p; sb  = sz; }
    }

    if (!(x && nvk == 2 && nj == 2 && nwk == 2 && nb == 4)) {
        if (n_in < 11) return;
        x     = (const float*)d_in[0];  sx  = in_sizes[0];
        vk[0] = (const float*)d_in[1];  bs[0] = (const float*)d_in[2];
        vk[1] = (const float*)d_in[3];  bs[1] = (const float*)d_in[4];
        J[0]  = (const float*)d_in[5];  J[1]  = (const float*)d_in[6];
        wk[0] = (const float*)d_in[7];  bs[2] = (const float*)d_in[8];
        wk[1] = (const float*)d_in[9];  bs[3] = (const float*)d_in[10];
        svk = in_sizes[1]; sj = in_sizes[5]; swk = in_sizes[7]; sb = in_sizes[2];
    }

    int mode       = (out_size == 2 * P_ * DM) ? 1 : 0;
    int out_floats = out_size;

    __nv_bfloat16 *wtR_hi_p, *wtR_lo_p, *wtI_hi_p, *wtI_lo_p;
    cudaGetSymbolAddress((void**)&wtR_hi_p, g_WtR_hi);
    cudaGetSymbolAddress((void**)&wtR_lo_p, g_WtR_lo);
    cudaGetSymbolAddress((void**)&wtI_hi_p, g_WtI_hi);
    cudaGetSymbolAddress((void**)&wtI_lo_p, g_WtI_lo);

    gemm_v  <<<dim3(DM / 64, P_ / 64, 2), 256>>>(x, sx, vk[0], bs[0], vk[1], bs[1],
                                                 svk, sb);
    circ_att<<<dim3(P_ / 64, H_), 256>>>(J[0], J[1], sj);
    split_y <<<(P_ * DM + 255) / 256, 256>>>();
    split_wt<<<dim3(DM / 32, DM / 32), dim3(32, 8)>>>(wk[0], swk, wtR_hi_p, wtR_lo_p);
    split_wt<<<dim3(DM / 32, DM / 32), dim3(32, 8)>>>(wk[1], swk, wtI_hi_p, wtI_lo_p);
    gemm_out_mma<<<dim3(DM / BN, P_ / BM), 128>>>(bs[2], bs[3], sb,
                                                  (float*)d_out, out_floats, mode);
}